// round 14
// baseline (speedup 1.0000x reference)
#include <cuda_runtime.h>
#include <cuda_fp16.h>
#include <math.h>
#include <stdint.h>
#include <stddef.h>

#define BATCH 2048
#define SEQ   64
#define CH    384
#define NH    12
#define HD    32
#define MTOT  (BATCH*SEQ)      // 131072
#define NQKV  (3*CH)           // 1152

// ---------------- static device scratch ------------------------------------
__device__ __half g_xh  [(size_t)MTOT * CH];     // fp16(x)
__device__ __half g_wqh [(size_t)NQKV * CH];     // permuted qkv_w^T [h*96+s*32+c][k]
__device__ __half g_wph [(size_t)CH * CH];       // proj_w^T [n][k]
__device__ __half g_t   [(size_t)MTOT * CH];     // fp16 attention output
__device__ float  g_lamc[NH];

// ---------------- PTX helpers ----------------------------------------------
static __device__ __forceinline__ uint32_t smem_u32(const void* p) {
    uint32_t a;
    asm("{ .reg .u64 t; cvta.to.shared.u64 t, %1; cvt.u32.u64 %0, t; }"
        : "=r"(a) : "l"(p));
    return a;
}
static __device__ __forceinline__ void cp_async16(uint32_t dst, const void* src) {
    asm volatile("cp.async.cg.shared.global [%0], [%1], 16;"
                 :: "r"(dst), "l"(src) : "memory");
}
static __device__ __forceinline__ void cp_commit() {
    asm volatile("cp.async.commit_group;" ::: "memory");
}
template <int N>
static __device__ __forceinline__ void cp_wait() {
    asm volatile("cp.async.wait_group %0;" :: "n"(N) : "memory");
}
static __device__ __forceinline__ void ldsm_x4(uint32_t* r, uint32_t addr) {
    asm volatile("ldmatrix.sync.aligned.m8n8.x4.shared.b16 {%0,%1,%2,%3}, [%4];"
                 : "=r"(r[0]), "=r"(r[1]), "=r"(r[2]), "=r"(r[3]) : "r"(addr));
}
static __device__ __forceinline__ void mma16816(float* d, const uint32_t* a,
                                                uint32_t b0, uint32_t b1) {
    asm volatile("mma.sync.aligned.m16n8k16.row.col.f32.f16.f16.f32 "
                 "{%0,%1,%2,%3}, {%4,%5,%6,%7}, {%8,%9}, {%0,%1,%2,%3};"
                 : "+f"(d[0]), "+f"(d[1]), "+f"(d[2]), "+f"(d[3])
                 : "r"(a[0]), "r"(a[1]), "r"(a[2]), "r"(a[3]), "r"(b0), "r"(b1));
}

// ---------------------------------------------------------------------------
// Kernel P: x -> fp16; qkv_w -> permuted/transposed fp16; proj_w -> transposed
// ---------------------------------------------------------------------------
__global__ void prep_kernel(const float* __restrict__ x,
                            const float* __restrict__ qkv_w,
                            const float* __restrict__ proj_w,
                            const float* __restrict__ lk1, const float* __restrict__ lv1,
                            const float* __restrict__ lk2, const float* __restrict__ lv2)
{
    const long long XN4 = (long long)MTOT * CH / 4;
    const long long WQ  = (long long)NQKV * CH;
    const long long WP  = (long long)CH * CH;
    const long long TOT = XN4 + WQ + WP + NH;
    long long stride = (long long)gridDim.x * blockDim.x;
    for (long long i = (long long)blockIdx.x * blockDim.x + threadIdx.x;
         i < TOT; i += stride) {
        if (i < XN4) {
            float4 v = __ldg(((const float4*)x) + i);
            __half2 p0 = __floats2half2_rn(v.x, v.y);
            __half2 p1 = __floats2half2_rn(v.z, v.w);
            uint2 pk;
            pk.x = *(uint32_t*)&p0;
            pk.y = *(uint32_t*)&p1;
            ((uint2*)g_xh)[i] = pk;
        } else if (i < XN4 + WQ) {
            long long j = i - XN4;
            int np = (int)(j / CH), k = (int)(j % CH);
            int h = np / 96, rem = np % 96;
            int s = rem / 32, c = rem % 32;
            int n = s * CH + h * HD + c;       // original qkv_w column
            float w = __ldg(qkv_w + (size_t)k * NQKV + n);
            g_wqh[j] = __float2half_rn(w);
        } else if (i < XN4 + WQ + WP) {
            long long j = i - XN4 - WQ;
            int n = (int)(j / CH), k = (int)(j % CH);
            float w = __ldg(proj_w + (size_t)k * CH + n);
            g_wph[j] = __float2half_rn(w);
        } else {
            int h = (int)(i - XN4 - WQ - WP);
            float s1 = 0.f, s2 = 0.f;
            for (int q = 0; q < HD; q++) {
                s1 += lk1[h*HD+q] * lv1[h*HD+q];
                s2 += lk2[h*HD+q] * lv2[h*HD+q];
            }
            float lam = expf(s1) - expf(s2) + 0.35550906759096926f;
            g_lamc[h] = (1.0f - lam) * 0.1767766952966369f;
        }
    }
}

// ---------------------------------------------------------------------------
// Persistent fused kernel: per-head weight tile resident in smem.
// grid (12 heads, 24); each CTA strides over m-blocks (mb += 24).
// Per m-block: qkv GEMM (M=128, N=96, K=384, A 2-stage cp.async) + bias +
// f-map + tensor-core linear attention -> g_t (fp16).  2 CTAs/SM.
// ---------------------------------------------------------------------------
#define RS      72                   // A-stage row stride in halves (144 B)
#define RSW     392                  // resident W row stride in halves (784 B)
#define W_B     (96 * RSW * 2)       // 75264 B
#define ASTG_B  (128 * RS * 2)       // 18432 B per A stage
#define OFF_A   W_B                  // A stages base (2 stages)
// attention scratch aliases the A-stage region:
#define OFF_Q   (W_B + 0)            // q_s  [128][40] halves = 10240 B
#define OFF_KT  (W_B + 10240)        // kT_s [32][136] halves = 8704 B
#define OFF_VT  (W_B + 18944)        // vT_s [32][136] halves = 8704 B
#define OFF_MT  (W_B + 27648)        // MT_s [64][40]  halves = 5120 B
#define OFF_GT  (W_B + 2 * ASTG_B)   // gtab [32] floats
#define SMEM1   (OFF_GT + 128)       // 112256 B  (x2 = 224.5 KB <= 228 KB)
#define MBLK    1024
#define NPCTA   24                   // qkv grid.y

__global__ __launch_bounds__(256, 2)
void qkv_attn(const __half* __restrict__ A,
              const __half* __restrict__ Wh,
              const float* __restrict__ qkv_b)
{
    extern __shared__ char smraw[];
    const uint32_t sbase = smem_u32(smraw);
    float*  gtab = (float*)(smraw + OFF_GT);

    const int tid  = threadIdx.x;
    const int lane = tid & 31;
    const int wid  = tid >> 5;
    const int wm   = wid >> 1;        // 0..3  (32 rows each)
    const int wn   = wid & 1;         // 0..1  (48 cols each)
    const int h    = blockIdx.x;

    if (tid < 32) gtab[tid] = expf(-2.0f * (float)(tid * tid));
    const float coef = g_lamc[h];

    const __half* Bh = Wh + (size_t)h * 96 * CH;

    // ---- load resident W tile once: 96 rows x 48 16B-segs = 4608, 18/thr ----
    #pragma unroll
    for (int i = 0; i < 18; i++) {
        int e = tid + i * 256;            // 0..4607
        int row = e / 48, seg = e % 48;
        cp_async16(sbase + row * (RSW * 2) + seg * 16,
                   Bh + (size_t)row * CH + seg * 8);
    }
    cp_commit();

    // A-stage cp.async mapping: 128 rows x 8 segs = 1024 transfers, 4/thread
    int ld_row[4], ld_seg[4];
    #pragma unroll
    for (int i = 0; i < 4; i++) {
        int e = tid + i * 256;
        ld_row[i] = e >> 3;
        ld_seg[i] = e & 7;
    }

    const uint32_t aBase = ((wm * 32 + (lane & 15)) * RS + (lane >> 4) * 8) * 2;
    const uint32_t bRowOff = ((wn * 48 + (lane & 7) + (lane >> 4) * 8) * RSW
                              + ((lane >> 3) & 1) * 8) * 2;

    #pragma unroll 1
    for (int mb = blockIdx.y; mb < MBLK; mb += NPCTA) {
        const int arow = mb * 128;

        auto load_A = [&](int c, int s) {
            const uint32_t stg = sbase + OFF_A + s * ASTG_B;
            #pragma unroll
            for (int i = 0; i < 4; i++) {
                cp_async16(stg + (ld_row[i] * RS + ld_seg[i] * 8) * 2,
                           A + (size_t)(arow + ld_row[i]) * CH
                             + c * 64 + ld_seg[i] * 8);
            }
            cp_commit();
        };

        float acc[2][6][4];
        #pragma unroll
        for (int a = 0; a < 2; a++)
            #pragma unroll
            for (int b = 0; b < 6; b++)
                #pragma unroll
                for (int cdx = 0; cdx < 4; cdx++) acc[a][b][cdx] = 0.f;

        load_A(0, 0);

        #pragma unroll 1
        for (int c = 0; c < 6; c++) {
            cp_wait<0>();
            __syncthreads();
            if (c + 1 < 6) load_A(c + 1, (c + 1) & 1);

            const uint32_t stgA = sbase + OFF_A + (c & 1) * ASTG_B;
            const uint32_t wCol = (uint32_t)(c * 128);
            #pragma unroll
            for (int ks = 0; ks < 4; ks++) {
                uint32_t afr[2][4], bhf[3][4];
                #pragma unroll
                for (int mt = 0; mt < 2; mt++)
                    ldsm_x4(afr[mt], stgA + aBase + mt * (16 * RS * 2) + ks * 32);
                #pragma unroll
                for (int nt2 = 0; nt2 < 3; nt2++)
                    ldsm_x4(bhf[nt2], sbase + bRowOff + nt2 * (16 * RSW * 2)
                                      + wCol + ks * 32);
                #pragma unroll
                for (int mt = 0; mt < 2; mt++)
                    #pragma unroll
                    for (int nt = 0; nt < 6; nt++)
                        mma16816(acc[mt][nt], afr[mt],
                                 bhf[nt >> 1][(nt & 1) * 2],
                                 bhf[nt >> 1][(nt & 1) * 2 + 1]);
            }
        }
        __syncthreads();

        // ---- epilogue: bias + feature map -> fp16 smem (mma-ready) ----
        #pragma unroll
        for (int mt = 0; mt < 2; mt++) {
            const int r0 = wm * 32 + mt * 16 + (lane >> 2);
            #pragma unroll
            for (int nt = 0; nt < 6; nt++) {
                const int c0 = wn * 48 + nt * 8 + (lane & 3) * 2;
                const int sseg = c0 >> 5;               // 0:q 1:k 2:v
                const int cc = c0 & 31;
                const int gb = sseg * CH + h * HD + cc;
                const float b0 = __ldg(qkv_b + gb), b1 = __ldg(qkv_b + gb + 1);
                #pragma unroll
                for (int hf = 0; hf < 2; hf++) {
                    const int r = r0 + hf * 8;
                    float v0 = acc[mt][nt][hf * 2 + 0] + b0;
                    float v1 = acc[mt][nt][hf * 2 + 1] + b1;
                    if (sseg == 0) {
                        __half2 p = __floats2half2_rn(v0, v1);
                        *(__half2*)(smraw + OFF_Q + (r * 40 + cc) * 2) = p;
                    } else {
                        v0 = (v0 >= 0.f) ? v0 + 1.f : expf(v0);
                        v1 = (v1 >= 0.f) ? v1 + 1.f : expf(v1);
                        __half* dst = (__half*)(smraw + (sseg == 1 ? OFF_KT : OFF_VT));
                        dst[cc * 136 + r]       = __float2half_rn(v0);
                        dst[(cc + 1) * 136 + r] = __float2half_rn(v1);
                    }
                }
            }
        }
        __syncthreads();

        // ---- attention: window w = wid>>2, 4 warps per window ----
        const int w  = wid >> 2;
        const int ww = wid & 3;

        // A = kT @ vT^T  (m=32 d, n=32 e, k=64 tokens); warp quadrant 16x16
        {
            const int amt = ww >> 1, ant = ww & 1;
            float dA[2][4];
            #pragma unroll
            for (int i = 0; i < 2; i++)
                #pragma unroll
                for (int j = 0; j < 4; j++) dA[i][j] = 0.f;

            const uint32_t aAddr0 = sbase + OFF_KT
                + ((amt * 16 + (lane & 15)) * 136 + w * 64 + (lane >> 4) * 8) * 2;
            const uint32_t bAddr0 = sbase + OFF_VT
                + ((ant * 16 + (lane & 7) + (lane >> 4) * 8) * 136
                   + w * 64 + ((lane >> 3) & 1) * 8) * 2;
            #pragma unroll
            for (int ks = 0; ks < 4; ks++) {
                uint32_t af[4], bf[4];
                ldsm_x4(af, aAddr0 + ks * 32);
                ldsm_x4(bf, bAddr0 + ks * 32);
                mma16816(dA[0], af, bf[0], bf[1]);
                mma16816(dA[1], af, bf[2], bf[3]);
            }
            // M^T[e][d] = A[d][e] * gauss(|d-e|) * coef
            __half* MT = (__half*)(smraw + OFF_MT);
            #pragma unroll
            for (int n2 = 0; n2 < 2; n2++)
                #pragma unroll
                for (int idx = 0; idx < 4; idx++) {
                    int d = amt * 16 + (lane >> 2) + (idx >> 1) * 8;
                    int e = ant * 16 + n2 * 8 + (lane & 3) * 2 + (idx & 1);
                    int ad = (d > e) ? (d - e) : (e - d);
                    float val = dA[n2][idx] * gtab[ad] * coef;
                    MT[(w * 32 + e) * 40 + d] = __float2half_rn(val);
                }
        }
        __syncthreads();

        // t = q @ M  (m=64 tokens, n=32 e, k=32 d); warp: 16 tokens
        {
            float dT[4][4];
            #pragma unroll
            for (int i = 0; i < 4; i++)
                #pragma unroll
                for (int j = 0; j < 4; j++) dT[i][j] = 0.f;

            const uint32_t qAddr0 = sbase + OFF_Q
                + ((w * 64 + ww * 16 + (lane & 15)) * 40 + (lane >> 4) * 8) * 2;
            const uint32_t mAddr0 = sbase + OFF_MT
                + ((w * 32 + (lane & 7) + (lane >> 4) * 8) * 40
                   + ((lane >> 3) & 1) * 8) * 2;
            #pragma unroll
            for (int ks = 0; ks < 2; ks++) {
                uint32_t af[4];
                ldsm_x4(af, qAddr0 + ks * 32);
                #pragma unroll
                for (int ng = 0; ng < 2; ng++) {
                    uint32_t bf[4];
                    ldsm_x4(bf, mAddr0 + ng * (16 * 40 * 2) + ks * 32);
                    mma16816(dT[ng * 2 + 0], af, bf[0], bf[1]);
                    mma16816(dT[ng * 2 + 1], af, bf[2], bf[3]);
                }
            }
            #pragma unroll
            for (int nt = 0; nt < 4; nt++)
                #pragma unroll
                for (int hf = 0; hf < 2; hf++) {
                    int tok = w * 64 + ww * 16 + (lane >> 2) + hf * 8;
                    int e = nt * 8 + (lane & 3) * 2;
                    __half2 p = __floats2half2_rn(dT[nt][hf * 2], dT[nt][hf * 2 + 1]);
                    *(__half2*)&g_t[(size_t)(arow + tok) * CH + h * HD + e] = p;
                }
        }
        __syncthreads();   // attention reads done before next mb's A loads
    }
}

// ---------------------------------------------------------------------------
// Persistent proj GEMM: out[M, 384] = g_t @ proj_w + proj_b
// grid (4 n-groups of 96, 74); each CTA: resident W tile 96x384, strides
// m-blocks by 74. M=128, 8 warps (4m x 2n). 2 CTAs/SM (296 = 148*2).
// ---------------------------------------------------------------------------
#define NPROJ   74
#define SMEM2   (W_B + 2 * ASTG_B + 128)   // same footprint as qkv kernel

__global__ __launch_bounds__(256, 2)
void gemm_proj(const __half* __restrict__ A,
               const __half* __restrict__ Wh,
               const float* __restrict__ bias,
               float* __restrict__ C)
{
    extern __shared__ char smraw2[];
    const uint32_t sbase = smem_u32(smraw2);
    const int tid  = threadIdx.x;
    const int lane = tid & 31;
    const int wid  = tid >> 5;
    const int wm   = wid >> 1;        // 0..3
    const int wn   = wid & 1;         // 0..1
    const int ng   = blockIdx.x;      // n-group (96 cols)
    const int brow = ng * 96;

    const __half* Bh = Wh + (size_t)brow * CH;

    // resident W tile: 96 rows x 48 segs
    #pragma unroll
    for (int i = 0; i < 18; i++) {
        int e = tid + i * 256;
        int row = e / 48, seg = e % 48;
        cp_async16(sbase + row * (RSW * 2) + seg * 16,
                   Bh + (size_t)row * CH + seg * 8);
    }
    cp_commit();

    int ld_row[4], ld_seg[4];
    #pragma unroll
    for (int i = 0; i < 4; i++) {
        int e = tid + i * 256;
        ld_row[i] = e >> 3;
        ld_seg[i] = e & 7;
    }

    const uint32_t aBase = ((wm * 32 + (lane & 15)) * RS + (lane >> 4) * 8) * 2;
    const uint32_t bRowOff = ((wn * 48 + (lane & 7) + (lane >> 4) * 8) * RSW
                              + ((lane >> 3) & 1) * 8) * 2;

    #pragma unroll 1
    for (int mb = blockIdx.y; mb < MBLK; mb += NPROJ) {
        const int arow = mb * 128;

        auto load_A = [&](int c, int s) {
            const uint32_t stg = sbase + OFF_A + s * ASTG_B;
            #pragma unroll
            for (int i = 0; i < 4; i++) {
                cp_async16(stg + (ld_row[i] * RS + ld_seg[i] * 8) * 2,
                           A + (size_t)(arow + ld_row[i]) * CH
                             + c * 64 + ld_seg[i] * 8);
            }
            cp_commit();
        };

        float acc[2][6][4];
        #pragma unroll
        for (int a = 0; a < 2; a++)
            #pragma unroll
            for (int b = 0; b < 6; b++)
                #pragma unroll
                for (int cdx = 0; cdx < 4; cdx++) acc[a][b][cdx] = 0.f;

        load_A(0, 0);

        #pragma unroll 1
        for (int c = 0; c < 6; c++) {
            cp_wait<0>();
            __syncthreads();
            if (c + 1 < 6) load_A(c + 1, (c + 1) & 1);

            const uint32_t stgA = sbase + OFF_A + (c & 1) * ASTG_B;
            const uint32_t wCol = (uint32_t)(c * 128);
            #pragma unroll
            for (int ks = 0; ks < 4; ks++) {
                uint32_t afr[2][4], bhf[3][4];
                #pragma unroll
                for (int mt = 0; mt < 2; mt++)
                    ldsm_x4(afr[mt], stgA + aBase + mt * (16 * RS * 2) + ks * 32);
                #pragma unroll
                for (int nt2 = 0; nt2 < 3; nt2++)
                    ldsm_x4(bhf[nt2], sbase + bRowOff + nt2 * (16 * RSW * 2)
                                      + wCol + ks * 32);
                #pragma unroll
                for (int mt = 0; mt < 2; mt++)
                    #pragma unroll
                    for (int nt = 0; nt < 6; nt++)
                        mma16816(acc[mt][nt], afr[mt],
                                 bhf[nt >> 1][(nt & 1) * 2],
                                 bhf[nt >> 1][(nt & 1) * 2 + 1]);
            }
        }
        __syncthreads();   // stage reads done before next mb overwrites

        // epilogue: bias + streaming store
        #pragma unroll
        for (int mt = 0; mt < 2; mt++) {
            const int r0 = arow + wm * 32 + mt * 16 + (lane >> 2);
            #pragma unroll
            for (int nt = 0; nt < 6; nt++) {
                const int n = brow + wn * 48 + nt * 8 + (lane & 3) * 2;
                const float b0 = __ldg(bias + n), b1 = __ldg(bias + n + 1);
                #pragma unroll
                for (int hf = 0; hf < 2; hf++) {
                    float v0 = acc[mt][nt][hf * 2 + 0] + b0;
                    float v1 = acc[mt][nt][hf * 2 + 1] + b1;
                    __stcs(reinterpret_cast<float2*>(
                        C + (size_t)(r0 + hf * 8) * CH + n), make_float2(v0, v1));
                }
            }
        }
    }
}

// ---------------------------------------------------------------------------
extern "C" void kernel_launch(void* const* d_in, const int* in_sizes, int n_in,
                              void* d_out, int out_size) {
    (void)in_sizes; (void)n_in; (void)out_size;
    const float* x      = (const float*)d_in[0];
    const float* qkv_w  = (const float*)d_in[1];
    const float* qkv_b  = (const float*)d_in[2];
    const float* proj_w = (const float*)d_in[3];
    const float* proj_b = (const float*)d_in[4];
    const float* lk1    = (const float*)d_in[5];
    const float* lv1    = (const float*)d_in[6];
    const float* lk2    = (const float*)d_in[7];
    const float* lv2    = (const float*)d_in[8];

    static int inited = 0;
    static __half *xh, *wqh, *wph, *th;
    if (!inited) {
        cudaGetSymbolAddress((void**)&xh,  g_xh);
        cudaGetSymbolAddress((void**)&wqh, g_wqh);
        cudaGetSymbolAddress((void**)&wph, g_wph);
        cudaGetSymbolAddress((void**)&th,  g_t);
        cudaFuncSetAttribute(qkv_attn,
                             cudaFuncAttributeMaxDynamicSharedMemorySize, SMEM1);
        cudaFuncSetAttribute(gemm_proj,
                             cudaFuncAttributeMaxDynamicSharedMemorySize, SMEM2);
        inited = 1;
    }

    prep_kernel<<<2048, 256>>>(x, qkv_w, proj_w, lk1, lv1, lk2, lv2);
    qkv_attn<<<dim3(NH, NPCTA), 256, SMEM1>>>(xh, wqh, qkv_b);
    gemm_proj<<<dim3(4, NPROJ), 256, SMEM2>>>(th, wph, proj_b, (float*)d_out);
}

// round 17
// speedup vs baseline: 1.1247x; 1.1247x over previous
#include <cuda_runtime.h>
#include <cuda_fp16.h>
#include <math.h>
#include <stdint.h>
#include <stddef.h>

#define BATCH 2048
#define SEQ   64
#define CH    384
#define NH    12
#define HD    32
#define MTOT  (BATCH*SEQ)      // 131072
#define NQKV  (3*CH)           // 1152

// ---------------- static device scratch ------------------------------------
__device__ __half g_xh  [(size_t)MTOT * CH];     // fp16(x)
__device__ __half g_wqh [(size_t)NQKV * CH];     // permuted qkv_w^T [h*96+s*32+c][k]
__device__ __half g_wph [(size_t)CH * CH];       // proj_w^T [n][k]
__device__ __half g_t   [(size_t)MTOT * CH];     // fp16 attention output
__device__ float  g_lamc[NH];

// ---------------- PTX helpers ----------------------------------------------
static __device__ __forceinline__ uint32_t smem_u32(const void* p) {
    uint32_t a;
    asm("{ .reg .u64 t; cvta.to.shared.u64 t, %1; cvt.u32.u64 %0, t; }"
        : "=r"(a) : "l"(p));
    return a;
}
static __device__ __forceinline__ void cp_async16(uint32_t dst, const void* src) {
    asm volatile("cp.async.cg.shared.global [%0], [%1], 16;"
                 :: "r"(dst), "l"(src) : "memory");
}
static __device__ __forceinline__ void cp_commit() {
    asm volatile("cp.async.commit_group;" ::: "memory");
}
template <int N>
static __device__ __forceinline__ void cp_wait() {
    asm volatile("cp.async.wait_group %0;" :: "n"(N) : "memory");
}
static __device__ __forceinline__ void ldsm_x4(uint32_t* r, uint32_t addr) {
    asm volatile("ldmatrix.sync.aligned.m8n8.x4.shared.b16 {%0,%1,%2,%3}, [%4];"
                 : "=r"(r[0]), "=r"(r[1]), "=r"(r[2]), "=r"(r[3]) : "r"(addr));
}
static __device__ __forceinline__ void mma16816(float* d, const uint32_t* a,
                                                uint32_t b0, uint32_t b1) {
    asm volatile("mma.sync.aligned.m16n8k16.row.col.f32.f16.f16.f32 "
                 "{%0,%1,%2,%3}, {%4,%5,%6,%7}, {%8,%9}, {%0,%1,%2,%3};"
                 : "+f"(d[0]), "+f"(d[1]), "+f"(d[2]), "+f"(d[3])
                 : "r"(a[0]), "r"(a[1]), "r"(a[2]), "r"(a[3]), "r"(b0), "r"(b1));
}

// ---------------------------------------------------------------------------
// Kernel P: x -> fp16; qkv_w -> permuted/transposed fp16; proj_w -> transposed
// ---------------------------------------------------------------------------
__global__ void prep_kernel(const float* __restrict__ x,
                            const float* __restrict__ qkv_w,
                            const float* __restrict__ proj_w,
                            const float* __restrict__ lk1, const float* __restrict__ lv1,
                            const float* __restrict__ lk2, const float* __restrict__ lv2)
{
    const long long XN4 = (long long)MTOT * CH / 4;
    const long long WQ  = (long long)NQKV * CH;
    const long long WP  = (long long)CH * CH;
    const long long TOT = XN4 + WQ + WP + NH;
    long long stride = (long long)gridDim.x * blockDim.x;
    for (long long i = (long long)blockIdx.x * blockDim.x + threadIdx.x;
         i < TOT; i += stride) {
        if (i < XN4) {
            float4 v = __ldg(((const float4*)x) + i);
            __half2 p0 = __floats2half2_rn(v.x, v.y);
            __half2 p1 = __floats2half2_rn(v.z, v.w);
            uint2 pk;
            pk.x = *(uint32_t*)&p0;
            pk.y = *(uint32_t*)&p1;
            ((uint2*)g_xh)[i] = pk;
        } else if (i < XN4 + WQ) {
            long long j = i - XN4;
            int np = (int)(j / CH), k = (int)(j % CH);
            int h = np / 96, rem = np % 96;
            int s = rem / 32, c = rem % 32;
            int n = s * CH + h * HD + c;       // original qkv_w column
            float w = __ldg(qkv_w + (size_t)k * NQKV + n);
            g_wqh[j] = __float2half_rn(w);
        } else if (i < XN4 + WQ + WP) {
            long long j = i - XN4 - WQ;
            int n = (int)(j / CH), k = (int)(j % CH);
            float w = __ldg(proj_w + (size_t)k * CH + n);
            g_wph[j] = __float2half_rn(w);
        } else {
            int h = (int)(i - XN4 - WQ - WP);
            float s1 = 0.f, s2 = 0.f;
            for (int q = 0; q < HD; q++) {
                s1 += lk1[h*HD+q] * lv1[h*HD+q];
                s2 += lk2[h*HD+q] * lv2[h*HD+q];
            }
            float lam = expf(s1) - expf(s2) + 0.35550906759096926f;
            g_lamc[h] = (1.0f - lam) * 0.1767766952966369f;
        }
    }
}

// ---------------------------------------------------------------------------
// Persistent fused kernel: per-head weight tile resident in smem.
// grid (12 heads, 24); each CTA strides over m-blocks (mb += 24).
// Per m-block: qkv GEMM (M=128, N=96, K=384, A 2-stage cp.async) + bias +
// f-map + tensor-core linear attention -> g_t (fp16).  2 CTAs/SM.
// ---------------------------------------------------------------------------
#define RS      72                   // A-stage row stride in halves (144 B)
#define RSW     392                  // resident W row stride in halves (784 B)
#define W_B     (96 * RSW * 2)       // 75264 B
#define ASTG_B  (128 * RS * 2)       // 18432 B per A stage
#define OFF_A   W_B                  // A stages base (2 stages)
// attention scratch aliases the A-stage region:
#define OFF_Q   (W_B + 0)            // q_s  [128][40] halves = 10240 B
#define OFF_KT  (W_B + 10240)        // kT_s [32][136] halves = 8704 B
#define OFF_VT  (W_B + 18944)        // vT_s [32][136] halves = 8704 B
#define OFF_MT  (W_B + 27648)        // MT_s [64][40]  halves = 5120 B
#define OFF_GT  (W_B + 2 * ASTG_B)   // gtab [32] floats
#define SMEM1   (OFF_GT + 128)       // 112256 B  (x2 = 224.5 KB <= 228 KB)
#define MBLK    1024
#define NPCTA   24                   // qkv grid.y

__global__ __launch_bounds__(256, 2)
void qkv_attn(const __half* __restrict__ A,
              const __half* __restrict__ Wh,
              const float* __restrict__ qkv_b)
{
    extern __shared__ char smraw[];
    const uint32_t sbase = smem_u32(smraw);
    float*  gtab = (float*)(smraw + OFF_GT);

    const int tid  = threadIdx.x;
    const int lane = tid & 31;
    const int wid  = tid >> 5;
    const int wm   = wid >> 1;        // 0..3  (32 rows each)
    const int wn   = wid & 1;         // 0..1  (48 cols each)
    const int h    = blockIdx.x;

    if (tid < 32) gtab[tid] = __expf(-2.0f * (float)(tid * tid));
    const float coef = g_lamc[h];

    const __half* Bh = Wh + (size_t)h * 96 * CH;

    // ---- load resident W tile once: 96 rows x 48 16B-segs = 4608, 18/thr ----
    #pragma unroll
    for (int i = 0; i < 18; i++) {
        int e = tid + i * 256;            // 0..4607
        int row = e / 48, seg = e % 48;
        cp_async16(sbase + row * (RSW * 2) + seg * 16,
                   Bh + (size_t)row * CH + seg * 8);
    }
    cp_commit();

    // A-stage cp.async mapping: 128 rows x 8 segs = 1024 transfers, 4/thread
    int ld_row[4], ld_seg[4];
    #pragma unroll
    for (int i = 0; i < 4; i++) {
        int e = tid + i * 256;
        ld_row[i] = e >> 3;
        ld_seg[i] = e & 7;
    }

    // hoisted per-thread epilogue constants (invariant over mb)
    int ep_sseg[6], ep_cc[6];
    float ep_b0[6], ep_b1[6];
    #pragma unroll
    for (int nt = 0; nt < 6; nt++) {
        const int c0 = wn * 48 + nt * 8 + (lane & 3) * 2;
        ep_sseg[nt] = c0 >> 5;
        ep_cc[nt]   = c0 & 31;
        const int gb = ep_sseg[nt] * CH + h * HD + ep_cc[nt];
        ep_b0[nt] = __ldg(qkv_b + gb);
        ep_b1[nt] = __ldg(qkv_b + gb + 1);
    }

    const uint32_t aBase = ((wm * 32 + (lane & 15)) * RS + (lane >> 4) * 8) * 2;
    const uint32_t bRowOff = ((wn * 48 + (lane & 7) + (lane >> 4) * 8) * RSW
                              + ((lane >> 3) & 1) * 8) * 2;

    #pragma unroll 1
    for (int mb = blockIdx.y; mb < MBLK; mb += NPCTA) {
        const int arow = mb * 128;

        auto load_A = [&](int c, int s) {
            const uint32_t stg = sbase + OFF_A + s * ASTG_B;
            #pragma unroll
            for (int i = 0; i < 4; i++) {
                cp_async16(stg + (ld_row[i] * RS + ld_seg[i] * 8) * 2,
                           A + (size_t)(arow + ld_row[i]) * CH
                             + c * 64 + ld_seg[i] * 8);
            }
            cp_commit();
        };

        float acc[2][6][4];
        #pragma unroll
        for (int a = 0; a < 2; a++)
            #pragma unroll
            for (int b = 0; b < 6; b++)
                #pragma unroll
                for (int cdx = 0; cdx < 4; cdx++) acc[a][b][cdx] = 0.f;

        load_A(0, 0);

        #pragma unroll 1
        for (int c = 0; c < 6; c++) {
            cp_wait<0>();
            __syncthreads();
            if (c + 1 < 6) load_A(c + 1, (c + 1) & 1);

            const uint32_t stgA = sbase + OFF_A + (c & 1) * ASTG_B;
            const uint32_t wCol = (uint32_t)(c * 128);
            #pragma unroll
            for (int ks = 0; ks < 4; ks++) {
                uint32_t afr[2][4], bhf[3][4];
                #pragma unroll
                for (int mt = 0; mt < 2; mt++)
                    ldsm_x4(afr[mt], stgA + aBase + mt * (16 * RS * 2) + ks * 32);
                #pragma unroll
                for (int nt2 = 0; nt2 < 3; nt2++)
                    ldsm_x4(bhf[nt2], sbase + bRowOff + nt2 * (16 * RSW * 2)
                                      + wCol + ks * 32);
                #pragma unroll
                for (int mt = 0; mt < 2; mt++)
                    #pragma unroll
                    for (int nt = 0; nt < 6; nt++)
                        mma16816(acc[mt][nt], afr[mt],
                                 bhf[nt >> 1][(nt & 1) * 2],
                                 bhf[nt >> 1][(nt & 1) * 2 + 1]);
            }
        }
        __syncthreads();

        // ---- epilogue: bias + feature map -> fp16 smem (mma-ready) ----
        #pragma unroll
        for (int mt = 0; mt < 2; mt++) {
            const int r0 = wm * 32 + mt * 16 + (lane >> 2);
            #pragma unroll
            for (int nt = 0; nt < 6; nt++) {
                const int sseg = ep_sseg[nt];
                const int cc = ep_cc[nt];
                const float b0 = ep_b0[nt], b1 = ep_b1[nt];
                #pragma unroll
                for (int hf = 0; hf < 2; hf++) {
                    const int r = r0 + hf * 8;
                    float v0 = acc[mt][nt][hf * 2 + 0] + b0;
                    float v1 = acc[mt][nt][hf * 2 + 1] + b1;
                    if (sseg == 0) {
                        __half2 p = __floats2half2_rn(v0, v1);
                        *(__half2*)(smraw + OFF_Q + (r * 40 + cc) * 2) = p;
                    } else {
                        v0 = (v0 >= 0.f) ? v0 + 1.f : __expf(v0);
                        v1 = (v1 >= 0.f) ? v1 + 1.f : __expf(v1);
                        __half* dst = (__half*)(smraw + (sseg == 1 ? OFF_KT : OFF_VT));
                        dst[cc * 136 + r]       = __float2half_rn(v0);
                        dst[(cc + 1) * 136 + r] = __float2half_rn(v1);
                    }
                }
            }
        }
        __syncthreads();

        // ---- attention: window w = wid>>2, 4 warps per window ----
        const int w  = wid >> 2;
        const int ww = wid & 3;

        // A = kT @ vT^T  (m=32 d, n=32 e, k=64 tokens); warp quadrant 16x16
        {
            const int amt = ww >> 1, ant = ww & 1;
            float dA[2][4];
            #pragma unroll
            for (int i = 0; i < 2; i++)
                #pragma unroll
                for (int j = 0; j < 4; j++) dA[i][j] = 0.f;

            const uint32_t aAddr0 = sbase + OFF_KT
                + ((amt * 16 + (lane & 15)) * 136 + w * 64 + (lane >> 4) * 8) * 2;
            const uint32_t bAddr0 = sbase + OFF_VT
                + ((ant * 16 + (lane & 7) + (lane >> 4) * 8) * 136
                   + w * 64 + ((lane >> 3) & 1) * 8) * 2;
            #pragma unroll
            for (int ks = 0; ks < 4; ks++) {
                uint32_t af[4], bf[4];
                ldsm_x4(af, aAddr0 + ks * 32);
                ldsm_x4(bf, bAddr0 + ks * 32);
                mma16816(dA[0], af, bf[0], bf[1]);
                mma16816(dA[1], af, bf[2], bf[3]);
            }
            // M^T[e][d] = A[d][e] * gauss(|d-e|) * coef
            __half* MT = (__half*)(smraw + OFF_MT);
            #pragma unroll
            for (int n2 = 0; n2 < 2; n2++)
                #pragma unroll
                for (int idx = 0; idx < 4; idx++) {
                    int d = amt * 16 + (lane >> 2) + (idx >> 1) * 8;
                    int e = ant * 16 + n2 * 8 + (lane & 3) * 2 + (idx & 1);
                    int ad = (d > e) ? (d - e) : (e - d);
                    float val = dA[n2][idx] * gtab[ad] * coef;
                    MT[(w * 32 + e) * 40 + d] = __float2half_rn(val);
                }
        }
        __syncthreads();

        // t = q @ M  (m=64 tokens, n=32 e, k=32 d); warp: 16 tokens
        {
            float dT[4][4];
            #pragma unroll
            for (int i = 0; i < 4; i++)
                #pragma unroll
                for (int j = 0; j < 4; j++) dT[i][j] = 0.f;

            const uint32_t qAddr0 = sbase + OFF_Q
                + ((w * 64 + ww * 16 + (lane & 15)) * 40 + (lane >> 4) * 8) * 2;
            const uint32_t mAddr0 = sbase + OFF_MT
                + ((w * 32 + (lane & 7) + (lane >> 4) * 8) * 40
                   + ((lane >> 3) & 1) * 8) * 2;
            #pragma unroll
            for (int ks = 0; ks < 2; ks++) {
                uint32_t af[4];
                ldsm_x4(af, qAddr0 + ks * 32);
                #pragma unroll
                for (int ng = 0; ng < 2; ng++) {
                    uint32_t bf[4];
                    ldsm_x4(bf, mAddr0 + ng * (16 * 40 * 2) + ks * 32);
                    mma16816(dT[ng * 2 + 0], af, bf[0], bf[1]);
                    mma16816(dT[ng * 2 + 1], af, bf[2], bf[3]);
                }
            }
            #pragma unroll
            for (int nt = 0; nt < 4; nt++)
                #pragma unroll
                for (int hf = 0; hf < 2; hf++) {
                    int tok = w * 64 + ww * 16 + (lane >> 2) + hf * 8;
                    int e = nt * 8 + (lane & 3) * 2;
                    __half2 p = __floats2half2_rn(dT[nt][hf * 2], dT[nt][hf * 2 + 1]);
                    *(__half2*)&g_t[(size_t)(arow + tok) * CH + h * HD + e] = p;
                }
        }
        __syncthreads();   // attention reads done before next mb's A loads
    }
}

// ---------------------------------------------------------------------------
// proj GEMM: out[M, 384] = g_t @ proj_w + proj_b  (fp16 mma, K-chunks of 64)
// CTA 128x128, 8 warps (2m x 4n), 3-stage pipeline, single barrier, 2 CTAs/SM
// ---------------------------------------------------------------------------
#define TILE_H2   (128 * RS)
#define STAGE_B2  (2 * TILE_H2 * 2)          // 36864 (A + B)
#define SMEM2     (3 * STAGE_B2)             // 110592

__global__ __launch_bounds__(256, 2)
void gemm_proj(const __half* __restrict__ A,
               const __half* __restrict__ Bh,
               const float* __restrict__ bias,
               float* __restrict__ C)
{
    extern __shared__ __half sm[];
    const uint32_t sbase = smem_u32(sm);
    const int tid  = threadIdx.x;
    const int lane = tid & 31;
    const int wid  = tid >> 5;
    const int wm   = wid >> 2;
    const int wn   = wid & 3;
    const int arow = blockIdx.y * 128;
    const int brow = blockIdx.x * 128;

    // 256 rows x 8 segs = 2048 transfers per stage, 8 per thread
    int ld_arr[8], ld_row[8], ld_seg[8];
    #pragma unroll
    for (int i = 0; i < 8; i++) {
        int e = tid + i * 256;
        ld_arr[i] = e >> 10;             // 0:A 1:B
        int idx = e & 1023;
        ld_row[i] = idx >> 3;
        ld_seg[i] = idx & 7;
    }

    auto load_stage = [&](int c, int s) {
        const uint32_t stg = sbase + s * STAGE_B2;
        #pragma unroll
        for (int i = 0; i < 8; i++) {
            const __half* gsrc;
            int row = ld_row[i];
            if (ld_arr[i] == 0) gsrc = A  + (size_t)(arow + row) * CH;
            else                gsrc = Bh + (size_t)(brow + row) * CH;
            gsrc += c * 64 + ld_seg[i] * 8;
            uint32_t dst = stg + (ld_arr[i] * TILE_H2 + row * RS + ld_seg[i] * 8) * 2;
            cp_async16(dst, gsrc);
        }
        cp_commit();
    };

    float acc[4][4][4];
    #pragma unroll
    for (int a = 0; a < 4; a++)
        #pragma unroll
        for (int b = 0; b < 4; b++)
            #pragma unroll
            for (int cdx = 0; cdx < 4; cdx++) acc[a][b][cdx] = 0.f;

    const uint32_t aBase = ((wm * 64 + (lane & 15)) * RS + (lane >> 4) * 8) * 2;
    const uint32_t bRowOff = ((wn * 32 + (lane & 7) + (lane >> 4) * 8) * RS
                              + ((lane >> 3) & 1) * 8) * 2;

    load_stage(0, 0);
    load_stage(1, 1);

    #pragma unroll 1
    for (int c = 0; c < 6; c++) {
        if (c < 5) cp_wait<1>(); else cp_wait<0>();
        __syncthreads();
        if (c + 2 < 6) load_stage(c + 2, (c + 2) % 3);

        const uint32_t stg = sbase + (c % 3) * STAGE_B2;
        #pragma unroll
        for (int ks = 0; ks < 4; ks++) {
            uint32_t afr[4][4], bhf[2][4];
            #pragma unroll
            for (int mt = 0; mt < 4; mt++)
                ldsm_x4(afr[mt], stg + aBase + mt * (16 * RS * 2) + ks * 32);
            #pragma unroll
            for (int nt2 = 0; nt2 < 2; nt2++)
                ldsm_x4(bhf[nt2], stg + TILE_H2 * 2 + bRowOff
                                  + nt2 * (16 * RS * 2) + ks * 32);
            #pragma unroll
            for (int mt = 0; mt < 4; mt++)
                #pragma unroll
                for (int nt = 0; nt < 4; nt++)
                    mma16816(acc[mt][nt], afr[mt],
                             bhf[nt >> 1][(nt & 1) * 2], bhf[nt >> 1][(nt & 1) * 2 + 1]);
        }
    }

    #pragma unroll
    for (int mt = 0; mt < 4; mt++) {
        const int r0 = arow + wm * 64 + mt * 16 + (lane >> 2);
        #pragma unroll
        for (int nt = 0; nt < 4; nt++) {
            const int n = brow + wn * 32 + nt * 8 + (lane & 3) * 2;
            const float b0 = __ldg(bias + n), b1 = __ldg(bias + n + 1);
            #pragma unroll
            for (int hf = 0; hf < 2; hf++) {
                float v0 = acc[mt][nt][hf * 2 + 0] + b0;
                float v1 = acc[mt][nt][hf * 2 + 1] + b1;
                __stcs(reinterpret_cast<float2*>(
                    C + (size_t)(r0 + hf * 8) * CH + n), make_float2(v0, v1));
            }
        }
    }
}

// ---------------------------------------------------------------------------
extern "C" void kernel_launch(void* const* d_in, const int* in_sizes, int n_in,
                              void* d_out, int out_size) {
    (void)in_sizes; (void)n_in; (void)out_size;
    const float* x      = (const float*)d_in[0];
    const float* qkv_w  = (const float*)d_in[1];
    const float* qkv_b  = (const float*)d_in[2];
    const float* proj_w = (const float*)d_in[3];
    const float* proj_b = (const float*)d_in[4];
    const float* lk1    = (const float*)d_in[5];
    const float* lv1    = (const float*)d_in[6];
    const float* lk2    = (const float*)d_in[7];
    const float* lv2    = (const float*)d_in[8];

    static int inited = 0;
    static __half *xh, *wqh, *wph, *th;
    if (!inited) {
        cudaGetSymbolAddress((void**)&xh,  g_xh);
        cudaGetSymbolAddress((void**)&wqh, g_wqh);
        cudaGetSymbolAddress((void**)&wph, g_wph);
        cudaGetSymbolAddress((void**)&th,  g_t);
        cudaFuncSetAttribute(qkv_attn,
                             cudaFuncAttributeMaxDynamicSharedMemorySize, SMEM1);
        cudaFuncSetAttribute(gemm_proj,
                             cudaFuncAttributeMaxDynamicSharedMemorySize, SMEM2);
        inited = 1;
    }

    prep_kernel<<<2048, 256>>>(x, qkv_w, proj_w, lk1, lv1, lk2, lv2);
    qkv_attn<<<dim3(NH, NPCTA), 256, SMEM1>>>(xh, wqh, qkv_b);
    gemm_proj<<<dim3(CH/128, MTOT/128), 256, SMEM2>>>(th, wph, proj_b,
                                                      (float*)d_out);
}